// round 12
// baseline (speedup 1.0000x reference)
#include <cuda_runtime.h>
#include <math.h>

#define NN 50000
#define EE 800000
#define ETOT (EE + NN)      // edges + self loops
#define FF 128              // HEADS*HID = F_IN
#define HH 4
#define NC 8

typedef unsigned long long ull;

// ---- scratch (device globals; no allocation allowed) ----
__device__ __align__(16) float g_htA[(size_t)NN * FF];  // layer-0 transformed
__device__ __align__(16) float g_htB[(size_t)NN * FF];  // layer-1 transformed
__device__ __align__(16) float g_feat[(size_t)NN * FF]; // layer-0 output
__device__ __align__(16) float g_h2[NN * NC];           // layer-2 transformed
__device__ __align__(16) float g_asA[NN * HH];
__device__ __align__(16) float g_adA[NN * HH];
__device__ __align__(16) float g_asB[NN * HH];
__device__ __align__(16) float g_adB[NN * HH];
__device__ __align__(16) float g_as2[NN];
__device__ __align__(16) float g_ad2[NN];
__device__ int g_srcp[ETOT];        // src per edge, sorted by dst (CSR)
__device__ int g_rowptr[NN + 1];    // CSR row pointers (by dst)
__device__ int g_deg[NN];
__device__ int g_ofs[NN];           // scatter cursors

// ---- packed f32x2 helpers (Blackwell FFMA2) ----
__device__ __forceinline__ ull fma2(ull a, ull b, ull c) {
    ull d;
    asm("fma.rn.f32x2 %0, %1, %2, %3;" : "=l"(d) : "l"(a), "l"(b), "l"(c));
    return d;
}
__device__ __forceinline__ ull pk2(float v) {
    ull d;
    asm("mov.b64 %0, {%1, %1};" : "=l"(d) : "f"(v));
    return d;
}
__device__ __forceinline__ float2 up2(ull a) {
    float2 r;
    asm("mov.b64 {%0, %1}, %2;" : "=f"(r.x), "=f"(r.y) : "l"(a));
    return r;
}

// ================= CSR construction =================
__global__ void k_deg(const int* __restrict__ ei) {
    int e = blockIdx.x * blockDim.x + threadIdx.x;
    if (e >= ETOT) return;
    int dst = (e < EE) ? ei[EE + e] : e - EE;
    atomicAdd(&g_deg[dst], 1);
}

// single-block scan, 4 elements/thread, chunked with carry
__global__ void k_scan() {
    __shared__ int wsum[32];
    __shared__ int carryS;
    int tid = threadIdx.x, lane = tid & 31, wid = tid >> 5;
    if (tid == 0) { carryS = 0; g_rowptr[0] = 0; }
    __syncthreads();
    for (int base = 0; base < NN; base += 4096) {
        int i0 = base + tid * 4;
        int d0 = (i0 + 0 < NN) ? g_deg[i0 + 0] : 0;
        int d1 = (i0 + 1 < NN) ? g_deg[i0 + 1] : 0;
        int d2 = (i0 + 2 < NN) ? g_deg[i0 + 2] : 0;
        int d3 = (i0 + 3 < NN) ? g_deg[i0 + 3] : 0;
        int v = d0 + d1 + d2 + d3;
        int x = v;
#pragma unroll
        for (int off = 1; off < 32; off <<= 1) {
            int t = __shfl_up_sync(0xffffffffu, x, off);
            if (lane >= off) x += t;
        }
        if (lane == 31) wsum[wid] = x;
        __syncthreads();
        if (wid == 0) {
            int w = wsum[lane];
#pragma unroll
            for (int off = 1; off < 32; off <<= 1) {
                int t = __shfl_up_sync(0xffffffffu, w, off);
                if (lane >= off) w += t;
            }
            wsum[lane] = w;
        }
        __syncthreads();
        int inc = x + (wid > 0 ? wsum[wid - 1] : 0);
        int carry = carryS;
        __syncthreads();
        int excl = carry + inc - v;
        int p0 = excl + d0, p1 = p0 + d1, p2 = p1 + d2, p3 = p2 + d3;
        if (i0 + 0 < NN) { g_rowptr[i0 + 1] = p0; g_ofs[i0 + 0] = excl; }
        if (i0 + 1 < NN) { g_rowptr[i0 + 2] = p1; g_ofs[i0 + 1] = p0; }
        if (i0 + 2 < NN) { g_rowptr[i0 + 3] = p2; g_ofs[i0 + 2] = p1; }
        if (i0 + 3 < NN) { g_rowptr[i0 + 4] = p3; g_ofs[i0 + 3] = p2; }
        if (tid == 1023) carryS = carry + inc;
        __syncthreads();
    }
}

__global__ void k_scatter(const int* __restrict__ ei) {
    int e = blockIdx.x * blockDim.x + threadIdx.x;
    if (e >= ETOT) return;
    int src, dst;
    if (e < EE) { src = ei[e]; dst = ei[EE + e]; } else { src = dst = e - EE; }
    int pos = atomicAdd(&g_ofs[dst], 1);
    g_srcp[pos] = src;
}

// ======== fused GEMM (128->128, f32x2 packed) + attention coefficients ========
// block = 128 thr (4 warps), 16 nodes/block, 4 nodes/warp, 4 cols (2xf32x2)/lane
__global__ __launch_bounds__(128) void k_gemm_attn(const float* __restrict__ X,
                                                   const float* __restrict__ W,
                                                   const float* __restrict__ as_,
                                                   const float* __restrict__ ad_,
                                                   float* __restrict__ oht,
                                                   float* __restrict__ oas,
                                                   float* __restrict__ oad,
                                                   int node0) {
    __shared__ __align__(16) float xs[16 * FF];
    int warp = threadIdx.x >> 5, lane = threadIdx.x & 31;
    int nb = node0 + blockIdx.x * 16;
    const float4* X4 = (const float4*)(X + (size_t)nb * FF);
    float4* xs4 = (float4*)xs;
    for (int i = threadIdx.x; i < 16 * 32; i += 128) xs4[i] = X4[i];
    __syncthreads();
    ull acc[4][2];
#pragma unroll
    for (int j = 0; j < 4; j++) { acc[j][0] = 0ull; acc[j][1] = 0ull; }
    const ulonglong2* W2 = (const ulonglong2*)W;
    int n0 = warp * 4;
#pragma unroll 4
    for (int k4 = 0; k4 < 32; k4++) {
        float4 xv[4];
#pragma unroll
        for (int j = 0; j < 4; j++) xv[j] = xs4[(n0 + j) * 32 + k4];
#pragma unroll
        for (int c = 0; c < 4; c++) {
            ulonglong2 w = W2[(size_t)(k4 * 4 + c) * 32 + lane];
#pragma unroll
            for (int j = 0; j < 4; j++) {
                float xj = (c == 0) ? xv[j].x : (c == 1) ? xv[j].y : (c == 2) ? xv[j].z : xv[j].w;
                ull xx = pk2(xj);
                acc[j][0] = fma2(w.x, xx, acc[j][0]);
                acc[j][1] = fma2(w.y, xx, acc[j][1]);
            }
        }
    }
    float4* O4 = (float4*)oht;
    float4 as4 = ((const float4*)as_)[lane];
    float4 ad4 = ((const float4*)ad_)[lane];
#pragma unroll
    for (int j = 0; j < 4; j++) {
        float2 lo = up2(acc[j][0]), hi = up2(acc[j][1]);
        float4 a = make_float4(lo.x, lo.y, hi.x, hi.y);
        O4[(size_t)(nb + n0 + j) * 32 + lane] = a;
        float ps = a.x * as4.x + a.y * as4.y + a.z * as4.z + a.w * as4.w;
        float pd = a.x * ad4.x + a.y * ad4.y + a.z * ad4.z + a.w * ad4.w;
#pragma unroll
        for (int off = 1; off < 8; off <<= 1) {
            ps += __shfl_xor_sync(0xffffffffu, ps, off);
            pd += __shfl_xor_sync(0xffffffffu, pd, off);
        }
        if ((lane & 7) == 0) {
            int h = lane >> 3;
            oas[(nb + n0 + j) * HH + h] = ps;
            oad[(nb + n0 + j) * HH + h] = pd;
        }
    }
}

// ======== CSR aggregation (warp per dst node) + bias + BN + ELU ========
// optionally fused layer-2 GEMM (128->8) + layer-2 attn coefficients
template <bool FUSE_L2>
__global__ __launch_bounds__(256) void k_agg4(const float* __restrict__ ht,
                                              const float* __restrict__ gas,
                                              const float* __restrict__ gad,
                                              const float* __restrict__ b,
                                              const float* __restrict__ g,
                                              const float* __restrict__ bb,
                                              const float* __restrict__ rm,
                                              const float* __restrict__ rv,
                                              const float* __restrict__ W2,
                                              const float* __restrict__ as2,
                                              const float* __restrict__ ad2,
                                              int node0) {
    __shared__ float4 s_ex[8][32];
    __shared__ int s_src[8][32];
    __shared__ float sW2t[NC][FF];
    int wid = threadIdx.x >> 5, lane = threadIdx.x & 31;
    if (FUSE_L2) {
        for (int i = threadIdx.x; i < FF * NC; i += 256) {
            int k = i >> 3, m = i & 7;
            sW2t[m][k] = W2[i];
        }
        __syncthreads();
    }
    int node = node0 + blockIdx.x * 8 + wid;
    int start = g_rowptr[node], end = g_rowptr[node + 1];
    float4 ad4 = ((const float4*)gad)[node];
    int hh = lane >> 3;
    float4 acc = make_float4(0.f, 0.f, 0.f, 0.f);
    float4 den = make_float4(0.f, 0.f, 0.f, 0.f);
    const float4* ht4 = (const float4*)ht;
    for (int base = start; base < end; base += 32) {
        int k = base + lane;
        float4 ex = make_float4(0.f, 0.f, 0.f, 0.f);
        int src = 0;
        if (k < end) {
            src = g_srcp[k];
            float4 a = ((const float4*)gas)[src];
            float4 v;
            v.x = a.x + ad4.x; v.y = a.y + ad4.y; v.z = a.z + ad4.z; v.w = a.w + ad4.w;
            v.x = v.x > 0.f ? v.x : 0.2f * v.x;
            v.y = v.y > 0.f ? v.y : 0.2f * v.y;
            v.z = v.z > 0.f ? v.z : 0.2f * v.z;
            v.w = v.w > 0.f ? v.w : 0.2f * v.w;
            ex.x = __expf(v.x); ex.y = __expf(v.y); ex.z = __expf(v.z); ex.w = __expf(v.w);
            den.x += ex.x; den.y += ex.y; den.z += ex.z; den.w += ex.w;
        }
        s_src[wid][lane] = src;
        s_ex[wid][lane] = ex;
        __syncwarp();
        int cnt = min(32, end - base);
#pragma unroll 8
        for (int j = 0; j < cnt; j++) {
            int sj = s_src[wid][j];
            float al = ((const float*)&s_ex[wid][j])[hh];
            float4 hv = ht4[(size_t)sj * 32 + lane];
            acc.x += al * hv.x; acc.y += al * hv.y;
            acc.z += al * hv.z; acc.w += al * hv.w;
        }
        __syncwarp();
    }
#pragma unroll
    for (int off = 16; off; off >>= 1) {
        den.x += __shfl_xor_sync(0xffffffffu, den.x, off);
        den.y += __shfl_xor_sync(0xffffffffu, den.y, off);
        den.z += __shfl_xor_sync(0xffffffffu, den.z, off);
        den.w += __shfl_xor_sync(0xffffffffu, den.w, off);
    }
    float d = hh == 0 ? den.x : hh == 1 ? den.y : hh == 2 ? den.z : den.w;
    float inv = 1.f / (d + 1e-16f);
    acc.x *= inv; acc.y *= inv; acc.z *= inv; acc.w *= inv;
    // bias + BN(eval) + ELU epilogue
    float4 B = ((const float4*)b)[lane],  G = ((const float4*)g)[lane];
    float4 BB = ((const float4*)bb)[lane], RM = ((const float4*)rm)[lane];
    float4 RV = ((const float4*)rv)[lane];
    float4 v;
    v.x = (acc.x + B.x - RM.x) * rsqrtf(RV.x + 1e-5f) * G.x + BB.x;
    v.y = (acc.y + B.y - RM.y) * rsqrtf(RV.y + 1e-5f) * G.y + BB.y;
    v.z = (acc.z + B.z - RM.z) * rsqrtf(RV.z + 1e-5f) * G.z + BB.z;
    v.w = (acc.w + B.w - RM.w) * rsqrtf(RV.w + 1e-5f) * G.w + BB.w;
    v.x = v.x > 0.f ? v.x : __expf(v.x) - 1.f;
    v.y = v.y > 0.f ? v.y : __expf(v.y) - 1.f;
    v.z = v.z > 0.f ? v.z : __expf(v.z) - 1.f;
    v.w = v.w > 0.f ? v.w : __expf(v.w) - 1.f;
    if (!FUSE_L2) {
        ((float4*)g_feat)[(size_t)node * 32 + lane] = v;
    } else {
        // layer-2 GEMM: h2[m] = sum_c v[c] * W2[c][m], warp-reduce over lanes
        float h[NC];
#pragma unroll
        for (int m = 0; m < NC; m++) {
            float4 w = ((const float4*)(sW2t[m]))[lane];
            float p = v.x * w.x + v.y * w.y + v.z * w.z + v.w * w.w;
#pragma unroll
            for (int off = 16; off; off >>= 1)
                p += __shfl_xor_sync(0xffffffffu, p, off);
            h[m] = p;
        }
        if (lane == 0) {
            float ps = 0.f, pd = 0.f;
#pragma unroll
            for (int m = 0; m < NC; m++) {
                g_h2[node * NC + m] = h[m];
                ps += h[m] * as2[m];
                pd += h[m] * ad2[m];
            }
            g_as2[node] = ps;
            g_ad2[node] = pd;
        }
    }
}

// ======== layer 2 CSR aggregation (single pass) + bias + log_softmax ========
__global__ __launch_bounds__(256) void k_agg1_final(const float* __restrict__ b2,
                                                    float* __restrict__ out) {
    int wid = threadIdx.x >> 5, lane = threadIdx.x & 31;
    int node = blockIdx.x * 8 + wid;
    int start = g_rowptr[node], end = g_rowptr[node + 1];
    float adv = g_ad2[node];
    float den = 0.f;
    float4 a0 = make_float4(0.f, 0.f, 0.f, 0.f), a1 = a0;
    const float4* h2 = (const float4*)g_h2;
    for (int k = start + lane; k < end; k += 32) {
        int src = g_srcp[k];
        float v = g_as2[src] + adv;
        v = v > 0.f ? v : 0.2f * v;
        float ex = __expf(v);
        den += ex;
        float4 v0 = h2[(size_t)src * 2];
        float4 v1 = h2[(size_t)src * 2 + 1];
        a0.x += ex * v0.x; a0.y += ex * v0.y; a0.z += ex * v0.z; a0.w += ex * v0.w;
        a1.x += ex * v1.x; a1.y += ex * v1.y; a1.z += ex * v1.z; a1.w += ex * v1.w;
    }
#pragma unroll
    for (int off = 16; off; off >>= 1) {
        den  += __shfl_xor_sync(0xffffffffu, den, off);
        a0.x += __shfl_xor_sync(0xffffffffu, a0.x, off);
        a0.y += __shfl_xor_sync(0xffffffffu, a0.y, off);
        a0.z += __shfl_xor_sync(0xffffffffu, a0.z, off);
        a0.w += __shfl_xor_sync(0xffffffffu, a0.w, off);
        a1.x += __shfl_xor_sync(0xffffffffu, a1.x, off);
        a1.y += __shfl_xor_sync(0xffffffffu, a1.y, off);
        a1.z += __shfl_xor_sync(0xffffffffu, a1.z, off);
        a1.w += __shfl_xor_sync(0xffffffffu, a1.w, off);
    }
    if (lane == 0) {
        float inv = 1.f / (den + 1e-16f);
        float v[NC] = { a0.x * inv + b2[0], a0.y * inv + b2[1],
                        a0.z * inv + b2[2], a0.w * inv + b2[3],
                        a1.x * inv + b2[4], a1.y * inv + b2[5],
                        a1.z * inv + b2[6], a1.w * inv + b2[7] };
        float mx = -INFINITY;
#pragma unroll
        for (int j = 0; j < NC; j++) mx = fmaxf(mx, v[j]);
        float s = 0.f;
#pragma unroll
        for (int j = 0; j < NC; j++) s += __expf(v[j] - mx);
        float ls = __logf(s) + mx;
#pragma unroll
        for (int j = 0; j < NC; j++) out[node * NC + j] = v[j] - ls;
    }
}

extern "C" void kernel_launch(void* const* d_in, const int* in_sizes, int n_in,
                              void* d_out, int out_size) {
    const float* x   = (const float*)d_in[0];
    const int*   ei  = (const int*)d_in[1];
    const float* W0  = (const float*)d_in[2];
    const float* as0 = (const float*)d_in[3];
    const float* ad0 = (const float*)d_in[4];
    const float* b0  = (const float*)d_in[5];
    const float* g0  = (const float*)d_in[6];
    const float* bb0 = (const float*)d_in[7];
    const float* rm0 = (const float*)d_in[8];
    const float* rv0 = (const float*)d_in[9];
    const float* W1  = (const float*)d_in[10];
    const float* as1 = (const float*)d_in[11];
    const float* ad1 = (const float*)d_in[12];
    const float* b1  = (const float*)d_in[13];
    const float* g1  = (const float*)d_in[14];
    const float* bb1 = (const float*)d_in[15];
    const float* rm1 = (const float*)d_in[16];
    const float* rv1 = (const float*)d_in[17];
    const float* W2  = (const float*)d_in[18];
    const float* as2 = (const float*)d_in[19];
    const float* ad2 = (const float*)d_in[20];
    const float* b2  = (const float*)d_in[21];
    float* out = (float*)d_out;

    float *htA, *htB, *feat, *asA, *adA, *asB, *adB;
    int* deg_ptr;
    cudaGetSymbolAddress((void**)&htA, g_htA);
    cudaGetSymbolAddress((void**)&htB, g_htB);
    cudaGetSymbolAddress((void**)&feat, g_feat);
    cudaGetSymbolAddress((void**)&asA, g_asA);
    cudaGetSymbolAddress((void**)&adA, g_adA);
    cudaGetSymbolAddress((void**)&asB, g_asB);
    cudaGetSymbolAddress((void**)&adB, g_adB);
    cudaGetSymbolAddress((void**)&deg_ptr, g_deg);

    // one-time side stream + events for fork-join inside graph capture
    static cudaStream_t s2 = nullptr;
    static cudaEvent_t evFork = nullptr, evJoin = nullptr, evG = nullptr;
    static cudaEvent_t evA[4] = {nullptr, nullptr, nullptr, nullptr};
    if (!s2) {
        cudaStreamCreateWithFlags(&s2, cudaStreamNonBlocking);
        cudaEventCreateWithFlags(&evFork, cudaEventDisableTiming);
        cudaEventCreateWithFlags(&evJoin, cudaEventDisableTiming);
        cudaEventCreateWithFlags(&evG, cudaEventDisableTiming);
        for (int i = 0; i < 4; i++)
            cudaEventCreateWithFlags(&evA[i], cudaEventDisableTiming);
    }

    const int TB = 256;
    // chunk boundaries (multiples of 16): 0,12512,25024,37536,50000
    const int BND[5] = {0, 12512, 25024, 37536, 50000};

    // ---- fork: CSR build on s2, concurrent with layer-0 GEMM on stream 0 ----
    cudaEventRecord(evFork, 0);
    cudaStreamWaitEvent(s2, evFork, 0);

    cudaMemsetAsync(deg_ptr, 0, NN * sizeof(int), s2);
    k_deg<<<(ETOT + TB - 1) / TB, TB, 0, s2>>>(ei);
    k_scan<<<1, 1024, 0, s2>>>();
    k_scatter<<<(ETOT + TB - 1) / TB, TB, 0, s2>>>(ei);
    cudaEventRecord(evJoin, s2);

    // ======== layer 0 GEMM (full, independent of CSR) ========
    k_gemm_attn<<<NN / 16, 128>>>(x, W0, as0, ad0, htA, asA, adA, 0);

    // ---- join: aggregation needs both CSR and GEMM results ----
    cudaStreamWaitEvent(0, evJoin, 0);

    // ======== layer 0 aggregation chunks, pipelined with layer-1 GEMM ========
    for (int i = 0; i < 4; i++) {
        int nodes = BND[i + 1] - BND[i];
        k_agg4<false><<<nodes / 8, TB>>>(htA, asA, adA,
                                         b0, g0, bb0, rm0, rv0,
                                         nullptr, nullptr, nullptr, BND[i]);
        cudaEventRecord(evA[i], 0);
        cudaStreamWaitEvent(s2, evA[i], 0);
        k_gemm_attn<<<nodes / 16, 128, 0, s2>>>(feat, W1, as1, ad1,
                                                htB, asB, adB, BND[i]);
    }
    cudaEventRecord(evG, s2);
    cudaStreamWaitEvent(0, evG, 0);

    // ======== layer 1 aggregation (+ fused layer-2 GEMM/attn) ========
    k_agg4<true><<<NN / 8, TB>>>(htB, asB, adB,
                                 b1, g1, bb1, rm1, rv1, W2, as2, ad2, 0);

    // ======== layer 2 aggregation + log_softmax ========
    k_agg1_final<<<NN / 8, TB>>>(b2, out);
}

// round 13
// speedup vs baseline: 1.1500x; 1.1500x over previous
#include <cuda_runtime.h>
#include <cuda_fp16.h>
#include <math.h>

#define NN 50000
#define EE 800000
#define ETOT (EE + NN)      // edges + self loops
#define FF 128              // HEADS*HID = F_IN
#define HH 4
#define NC 8

typedef unsigned long long ull;

// ---- scratch (device globals; no allocation allowed) ----
__device__ __align__(16) __half g_ht[(size_t)NN * FF];  // transformed features (fp16)
__device__ __align__(16) float g_feat[(size_t)NN * FF]; // layer-0 output (fp32)
__device__ __align__(16) float g_h2[NN * NC];           // layer-2 transformed
__device__ __align__(16) float g_as[NN * HH];
__device__ __align__(16) float g_ad[NN * HH];
__device__ __align__(16) float g_as2[NN];
__device__ __align__(16) float g_ad2[NN];
__device__ int g_srcp[ETOT];        // src per edge, sorted by dst (CSR)
__device__ int g_rowptr[NN + 1];    // CSR row pointers (by dst)
__device__ int g_deg[NN];
__device__ int g_ofs[NN];           // scatter cursors

// ---- packed f32x2 helpers (Blackwell FFMA2) ----
__device__ __forceinline__ ull fma2(ull a, ull b, ull c) {
    ull d;
    asm("fma.rn.f32x2 %0, %1, %2, %3;" : "=l"(d) : "l"(a), "l"(b), "l"(c));
    return d;
}
__device__ __forceinline__ ull pk2(float v) {
    ull d;
    asm("mov.b64 %0, {%1, %1};" : "=l"(d) : "f"(v));
    return d;
}
__device__ __forceinline__ float2 up2(ull a) {
    float2 r;
    asm("mov.b64 {%0, %1}, %2;" : "=f"(r.x), "=f"(r.y) : "l"(a));
    return r;
}

// ================= CSR construction =================
__global__ void k_deg(const int* __restrict__ ei) {
    int e = blockIdx.x * blockDim.x + threadIdx.x;
    if (e >= ETOT) return;
    int dst = (e < EE) ? ei[EE + e] : e - EE;
    atomicAdd(&g_deg[dst], 1);
}

// single-block scan, 4 elements/thread, chunked with carry
__global__ void k_scan() {
    __shared__ int wsum[32];
    __shared__ int carryS;
    int tid = threadIdx.x, lane = tid & 31, wid = tid >> 5;
    if (tid == 0) { carryS = 0; g_rowptr[0] = 0; }
    __syncthreads();
    for (int base = 0; base < NN; base += 4096) {
        int i0 = base + tid * 4;
        int d0 = (i0 + 0 < NN) ? g_deg[i0 + 0] : 0;
        int d1 = (i0 + 1 < NN) ? g_deg[i0 + 1] : 0;
        int d2 = (i0 + 2 < NN) ? g_deg[i0 + 2] : 0;
        int d3 = (i0 + 3 < NN) ? g_deg[i0 + 3] : 0;
        int v = d0 + d1 + d2 + d3;
        int x = v;
#pragma unroll
        for (int off = 1; off < 32; off <<= 1) {
            int t = __shfl_up_sync(0xffffffffu, x, off);
            if (lane >= off) x += t;
        }
        if (lane == 31) wsum[wid] = x;
        __syncthreads();
        if (wid == 0) {
            int w = wsum[lane];
#pragma unroll
            for (int off = 1; off < 32; off <<= 1) {
                int t = __shfl_up_sync(0xffffffffu, w, off);
                if (lane >= off) w += t;
            }
            wsum[lane] = w;
        }
        __syncthreads();
        int inc = x + (wid > 0 ? wsum[wid - 1] : 0);
        int carry = carryS;
        __syncthreads();
        int excl = carry + inc - v;
        int p0 = excl + d0, p1 = p0 + d1, p2 = p1 + d2, p3 = p2 + d3;
        if (i0 + 0 < NN) { g_rowptr[i0 + 1] = p0; g_ofs[i0 + 0] = excl; }
        if (i0 + 1 < NN) { g_rowptr[i0 + 2] = p1; g_ofs[i0 + 1] = p0; }
        if (i0 + 2 < NN) { g_rowptr[i0 + 3] = p2; g_ofs[i0 + 2] = p1; }
        if (i0 + 3 < NN) { g_rowptr[i0 + 4] = p3; g_ofs[i0 + 3] = p2; }
        if (tid == 1023) carryS = carry + inc;
        __syncthreads();
    }
}

__global__ void k_scatter(const int* __restrict__ ei) {
    int e = blockIdx.x * blockDim.x + threadIdx.x;
    if (e >= ETOT) return;
    int src, dst;
    if (e < EE) { src = ei[e]; dst = ei[EE + e]; } else { src = dst = e - EE; }
    int pos = atomicAdd(&g_ofs[dst], 1);
    g_srcp[pos] = src;
}

// ======== fused GEMM (128->128, f32x2 packed) + attention coefficients ========
// block = 128 thr (4 warps), 16 nodes/block, 4 nodes/warp, 4 cols (2xf32x2)/lane
// h stored as fp16 (only consumed by the gather); attn coefs from fp32 accs.
__global__ __launch_bounds__(128) void k_gemm_attn(const float* __restrict__ X,
                                                   const float* __restrict__ W,
                                                   const float* __restrict__ as_,
                                                   const float* __restrict__ ad_) {
    __shared__ __align__(16) float xs[16 * FF];
    int warp = threadIdx.x >> 5, lane = threadIdx.x & 31;
    int nb = blockIdx.x * 16;
    const float4* X4 = (const float4*)(X + (size_t)nb * FF);
    float4* xs4 = (float4*)xs;
    for (int i = threadIdx.x; i < 16 * 32; i += 128) xs4[i] = X4[i];
    __syncthreads();
    ull acc[4][2];
#pragma unroll
    for (int j = 0; j < 4; j++) { acc[j][0] = 0ull; acc[j][1] = 0ull; }
    const ulonglong2* W2 = (const ulonglong2*)W;
    int n0 = warp * 4;
#pragma unroll 4
    for (int k4 = 0; k4 < 32; k4++) {
        float4 xv[4];
#pragma unroll
        for (int j = 0; j < 4; j++) xv[j] = xs4[(n0 + j) * 32 + k4];
#pragma unroll
        for (int c = 0; c < 4; c++) {
            ulonglong2 w = W2[(size_t)(k4 * 4 + c) * 32 + lane];
#pragma unroll
            for (int j = 0; j < 4; j++) {
                float xj = (c == 0) ? xv[j].x : (c == 1) ? xv[j].y : (c == 2) ? xv[j].z : xv[j].w;
                ull xx = pk2(xj);
                acc[j][0] = fma2(w.x, xx, acc[j][0]);
                acc[j][1] = fma2(w.y, xx, acc[j][1]);
            }
        }
    }
    uint2* O2 = (uint2*)g_ht;
    float4 as4 = ((const float4*)as_)[lane];
    float4 ad4 = ((const float4*)ad_)[lane];
#pragma unroll
    for (int j = 0; j < 4; j++) {
        float2 lo = up2(acc[j][0]), hi = up2(acc[j][1]);
        float4 a = make_float4(lo.x, lo.y, hi.x, hi.y);
        uint2 pk;
        *reinterpret_cast<__half2*>(&pk.x) = __floats2half2_rn(a.x, a.y);
        *reinterpret_cast<__half2*>(&pk.y) = __floats2half2_rn(a.z, a.w);
        O2[(size_t)(nb + n0 + j) * 32 + lane] = pk;
        float ps = a.x * as4.x + a.y * as4.y + a.z * as4.z + a.w * as4.w;
        float pd = a.x * ad4.x + a.y * ad4.y + a.z * ad4.z + a.w * ad4.w;
#pragma unroll
        for (int off = 1; off < 8; off <<= 1) {
            ps += __shfl_xor_sync(0xffffffffu, ps, off);
            pd += __shfl_xor_sync(0xffffffffu, pd, off);
        }
        if ((lane & 7) == 0) {
            int h = lane >> 3;
            g_as[(nb + n0 + j) * HH + h] = ps;
            g_ad[(nb + n0 + j) * HH + h] = pd;
        }
    }
}

// ======== CSR aggregation (warp per dst node) + bias + BN + ELU ========
// fp16 gather, fp32 accumulate; optionally fused layer-2 GEMM + attn coefs
template <bool FUSE_L2>
__global__ __launch_bounds__(256) void k_agg4(const float* __restrict__ b,
                                              const float* __restrict__ g,
                                              const float* __restrict__ bb,
                                              const float* __restrict__ rm,
                                              const float* __restrict__ rv,
                                              const float* __restrict__ W2,
                                              const float* __restrict__ as2,
                                              const float* __restrict__ ad2) {
    __shared__ float4 s_ex[8][32];
    __shared__ int s_src[8][32];
    __shared__ float sW2t[NC][FF];
    int wid = threadIdx.x >> 5, lane = threadIdx.x & 31;
    if (FUSE_L2) {
        for (int i = threadIdx.x; i < FF * NC; i += 256) {
            int k = i >> 3, m = i & 7;
            sW2t[m][k] = W2[i];
        }
        __syncthreads();
    }
    int node = blockIdx.x * 8 + wid;
    int start = g_rowptr[node], end = g_rowptr[node + 1];
    float4 ad4 = ((const float4*)g_ad)[node];
    int hh = lane >> 3;
    float4 acc = make_float4(0.f, 0.f, 0.f, 0.f);
    float4 den = make_float4(0.f, 0.f, 0.f, 0.f);
    const uint2* ht2 = (const uint2*)g_ht;
    for (int base = start; base < end; base += 32) {
        int k = base + lane;
        float4 ex = make_float4(0.f, 0.f, 0.f, 0.f);
        int src = 0;
        if (k < end) {
            src = g_srcp[k];
            float4 a = ((const float4*)g_as)[src];
            float4 v;
            v.x = a.x + ad4.x; v.y = a.y + ad4.y; v.z = a.z + ad4.z; v.w = a.w + ad4.w;
            v.x = v.x > 0.f ? v.x : 0.2f * v.x;
            v.y = v.y > 0.f ? v.y : 0.2f * v.y;
            v.z = v.z > 0.f ? v.z : 0.2f * v.z;
            v.w = v.w > 0.f ? v.w : 0.2f * v.w;
            ex.x = __expf(v.x); ex.y = __expf(v.y); ex.z = __expf(v.z); ex.w = __expf(v.w);
            den.x += ex.x; den.y += ex.y; den.z += ex.z; den.w += ex.w;
        }
        s_src[wid][lane] = src;
        s_ex[wid][lane] = ex;
        __syncwarp();
        int cnt = min(32, end - base);
#pragma unroll 8
        for (int j = 0; j < cnt; j++) {
            int sj = s_src[wid][j];
            float al = ((const float*)&s_ex[wid][j])[hh];
            uint2 hv = ht2[(size_t)sj * 32 + lane];
            float2 f0 = __half22float2(*reinterpret_cast<__half2*>(&hv.x));
            float2 f1 = __half22float2(*reinterpret_cast<__half2*>(&hv.y));
            acc.x += al * f0.x; acc.y += al * f0.y;
            acc.z += al * f1.x; acc.w += al * f1.y;
        }
        __syncwarp();
    }
#pragma unroll
    for (int off = 16; off; off >>= 1) {
        den.x += __shfl_xor_sync(0xffffffffu, den.x, off);
        den.y += __shfl_xor_sync(0xffffffffu, den.y, off);
        den.z += __shfl_xor_sync(0xffffffffu, den.z, off);
        den.w += __shfl_xor_sync(0xffffffffu, den.w, off);
    }
    float d = hh == 0 ? den.x : hh == 1 ? den.y : hh == 2 ? den.z : den.w;
    float inv = 1.f / (d + 1e-16f);
    acc.x *= inv; acc.y *= inv; acc.z *= inv; acc.w *= inv;
    // bias + BN(eval) + ELU epilogue
    float4 B = ((const float4*)b)[lane],  G = ((const float4*)g)[lane];
    float4 BB = ((const float4*)bb)[lane], RM = ((const float4*)rm)[lane];
    float4 RV = ((const float4*)rv)[lane];
    float4 v;
    v.x = (acc.x + B.x - RM.x) * rsqrtf(RV.x + 1e-5f) * G.x + BB.x;
    v.y = (acc.y + B.y - RM.y) * rsqrtf(RV.y + 1e-5f) * G.y + BB.y;
    v.z = (acc.z + B.z - RM.z) * rsqrtf(RV.z + 1e-5f) * G.z + BB.z;
    v.w = (acc.w + B.w - RM.w) * rsqrtf(RV.w + 1e-5f) * G.w + BB.w;
    v.x = v.x > 0.f ? v.x : __expf(v.x) - 1.f;
    v.y = v.y > 0.f ? v.y : __expf(v.y) - 1.f;
    v.z = v.z > 0.f ? v.z : __expf(v.z) - 1.f;
    v.w = v.w > 0.f ? v.w : __expf(v.w) - 1.f;
    if (!FUSE_L2) {
        ((float4*)g_feat)[(size_t)node * 32 + lane] = v;
    } else {
        // layer-2 GEMM: h2[m] = sum_c v[c] * W2[c][m], warp-reduce over lanes
        float h[NC];
#pragma unroll
        for (int m = 0; m < NC; m++) {
            float4 w = ((const float4*)(sW2t[m]))[lane];
            float p = v.x * w.x + v.y * w.y + v.z * w.z + v.w * w.w;
#pragma unroll
            for (int off = 16; off; off >>= 1)
                p += __shfl_xor_sync(0xffffffffu, p, off);
            h[m] = p;
        }
        if (lane == 0) {
            float ps = 0.f, pd = 0.f;
#pragma unroll
            for (int m = 0; m < NC; m++) {
                g_h2[node * NC + m] = h[m];
                ps += h[m] * as2[m];
                pd += h[m] * ad2[m];
            }
            g_as2[node] = ps;
            g_ad2[node] = pd;
        }
    }
}

// ======== layer 2 CSR aggregation (single pass) + bias + log_softmax ========
__global__ __launch_bounds__(256) void k_agg1_final(const float* __restrict__ b2,
                                                    float* __restrict__ out) {
    int wid = threadIdx.x >> 5, lane = threadIdx.x & 31;
    int node = blockIdx.x * 8 + wid;
    int start = g_rowptr[node], end = g_rowptr[node + 1];
    float adv = g_ad2[node];
    float den = 0.f;
    float4 a0 = make_float4(0.f, 0.f, 0.f, 0.f), a1 = a0;
    const float4* h2 = (const float4*)g_h2;
    for (int k = start + lane; k < end; k += 32) {
        int src = g_srcp[k];
        float v = g_as2[src] + adv;
        v = v > 0.f ? v : 0.2f * v;
        float ex = __expf(v);
        den += ex;
        float4 v0 = h2[(size_t)src * 2];
        float4 v1 = h2[(size_t)src * 2 + 1];
        a0.x += ex * v0.x; a0.y += ex * v0.y; a0.z += ex * v0.z; a0.w += ex * v0.w;
        a1.x += ex * v1.x; a1.y += ex * v1.y; a1.z += ex * v1.z; a1.w += ex * v1.w;
    }
#pragma unroll
    for (int off = 16; off; off >>= 1) {
        den  += __shfl_xor_sync(0xffffffffu, den, off);
        a0.x += __shfl_xor_sync(0xffffffffu, a0.x, off);
        a0.y += __shfl_xor_sync(0xffffffffu, a0.y, off);
        a0.z += __shfl_xor_sync(0xffffffffu, a0.z, off);
        a0.w += __shfl_xor_sync(0xffffffffu, a0.w, off);
        a1.x += __shfl_xor_sync(0xffffffffu, a1.x, off);
        a1.y += __shfl_xor_sync(0xffffffffu, a1.y, off);
        a1.z += __shfl_xor_sync(0xffffffffu, a1.z, off);
        a1.w += __shfl_xor_sync(0xffffffffu, a1.w, off);
    }
    if (lane == 0) {
        float inv = 1.f / (den + 1e-16f);
        float v[NC] = { a0.x * inv + b2[0], a0.y * inv + b2[1],
                        a0.z * inv + b2[2], a0.w * inv + b2[3],
                        a1.x * inv + b2[4], a1.y * inv + b2[5],
                        a1.z * inv + b2[6], a1.w * inv + b2[7] };
        float mx = -INFINITY;
#pragma unroll
        for (int j = 0; j < NC; j++) mx = fmaxf(mx, v[j]);
        float s = 0.f;
#pragma unroll
        for (int j = 0; j < NC; j++) s += __expf(v[j] - mx);
        float ls = __logf(s) + mx;
#pragma unroll
        for (int j = 0; j < NC; j++) out[node * NC + j] = v[j] - ls;
    }
}

extern "C" void kernel_launch(void* const* d_in, const int* in_sizes, int n_in,
                              void* d_out, int out_size) {
    const float* x   = (const float*)d_in[0];
    const int*   ei  = (const int*)d_in[1];
    const float* W0  = (const float*)d_in[2];
    const float* as0 = (const float*)d_in[3];
    const float* ad0 = (const float*)d_in[4];
    const float* b0  = (const float*)d_in[5];
    const float* g0  = (const float*)d_in[6];
    const float* bb0 = (const float*)d_in[7];
    const float* rm0 = (const float*)d_in[8];
    const float* rv0 = (const float*)d_in[9];
    const float* W1  = (const float*)d_in[10];
    const float* as1 = (const float*)d_in[11];
    const float* ad1 = (const float*)d_in[12];
    const float* b1  = (const float*)d_in[13];
    const float* g1  = (const float*)d_in[14];
    const float* bb1 = (const float*)d_in[15];
    const float* rm1 = (const float*)d_in[16];
    const float* rv1 = (const float*)d_in[17];
    const float* W2  = (const float*)d_in[18];
    const float* as2 = (const float*)d_in[19];
    const float* ad2 = (const float*)d_in[20];
    const float* b2  = (const float*)d_in[21];
    float* out = (float*)d_out;

    float* feat_ptr = nullptr;
    cudaGetSymbolAddress((void**)&feat_ptr, g_feat);
    int* deg_ptr = nullptr;
    cudaGetSymbolAddress((void**)&deg_ptr, g_deg);

    // one-time side stream + events for fork-join inside graph capture
    static cudaStream_t s2 = nullptr;
    static cudaEvent_t evFork = nullptr, evJoin = nullptr;
    if (!s2) {
        cudaStreamCreateWithFlags(&s2, cudaStreamNonBlocking);
        cudaEventCreateWithFlags(&evFork, cudaEventDisableTiming);
        cudaEventCreateWithFlags(&evJoin, cudaEventDisableTiming);
    }

    const int TB = 256;

    // ---- fork: CSR build on s2, concurrent with layer-0 GEMM on stream 0 ----
    cudaEventRecord(evFork, 0);
    cudaStreamWaitEvent(s2, evFork, 0);

    cudaMemsetAsync(deg_ptr, 0, NN * sizeof(int), s2);
    k_deg<<<(ETOT + TB - 1) / TB, TB, 0, s2>>>(ei);
    k_scan<<<1, 1024, 0, s2>>>();
    k_scatter<<<(ETOT + TB - 1) / TB, TB, 0, s2>>>(ei);
    cudaEventRecord(evJoin, s2);

    // ======== layer 0 GEMM (independent of CSR) ========
    k_gemm_attn<<<NN / 16, 128>>>(x, W0, as0, ad0);

    // ---- join: aggregation needs both CSR and GEMM results ----
    cudaStreamWaitEvent(0, evJoin, 0);

    k_agg4<false><<<NN / 8, TB>>>(b0, g0, bb0, rm0, rv0, nullptr, nullptr, nullptr);

    // ======== layer 1 (+ fused layer-2 GEMM/attn) ========
    k_gemm_attn<<<NN / 16, 128>>>(feat_ptr, W1, as1, ad1);
    k_agg4<true><<<NN / 8, TB>>>(b1, g1, bb1, rm1, rv1, W2, as2, ad2);

    // ======== layer 2 aggregation + log_softmax ========
    k_agg1_final<<<NN / 8, TB>>>(b2, out);
}

// round 14
// speedup vs baseline: 1.2001x; 1.0436x over previous
#include <cuda_runtime.h>
#include <cuda_fp16.h>
#include <math.h>

#define NN 50000
#define EE 800000
#define ETOT (EE + NN)      // edges + self loops
#define FF 128              // HEADS*HID = F_IN
#define HH 4
#define NC 8

typedef unsigned long long ull;

// ---- scratch (device globals; no allocation allowed) ----
__device__ __align__(16) __half g_ht[(size_t)NN * FF];   // transformed features (fp16)
__device__ __align__(16) __half g_feat[(size_t)NN * FF]; // layer-0 output (fp16)
__device__ __align__(16) __half g_h2[NN * NC];           // layer-2 transformed (fp16)
__device__ __align__(16) float g_as[NN * HH];
__device__ __align__(16) float g_ad[NN * HH];
__device__ __align__(16) float g_as2[NN];
__device__ __align__(16) float g_ad2[NN];
__device__ int g_srcp[ETOT];        // src per edge, sorted by dst (CSR)
__device__ int g_rowptr[NN + 1];    // CSR row pointers (by dst)
__device__ int g_deg[NN];
__device__ int g_ofs[NN];           // scatter cursors

// ---- packed f32x2 helpers (Blackwell FFMA2) ----
__device__ __forceinline__ ull fma2(ull a, ull b, ull c) {
    ull d;
    asm("fma.rn.f32x2 %0, %1, %2, %3;" : "=l"(d) : "l"(a), "l"(b), "l"(c));
    return d;
}
__device__ __forceinline__ ull pk2(float v) {
    ull d;
    asm("mov.b64 %0, {%1, %1};" : "=l"(d) : "f"(v));
    return d;
}
__device__ __forceinline__ float2 up2(ull a) {
    float2 r;
    asm("mov.b64 {%0, %1}, %2;" : "=f"(r.x), "=f"(r.y) : "l"(a));
    return r;
}

// ================= CSR construction =================
__global__ void k_deg(const int* __restrict__ ei) {
    int e = blockIdx.x * blockDim.x + threadIdx.x;
    if (e >= ETOT) return;
    int dst = (e < EE) ? ei[EE + e] : e - EE;
    atomicAdd(&g_deg[dst], 1);
}

// single-block scan, 4 elements/thread, chunked with carry
__global__ void k_scan() {
    __shared__ int wsum[32];
    __shared__ int carryS;
    int tid = threadIdx.x, lane = tid & 31, wid = tid >> 5;
    if (tid == 0) { carryS = 0; g_rowptr[0] = 0; }
    __syncthreads();
    for (int base = 0; base < NN; base += 4096) {
        int i0 = base + tid * 4;
        int d0 = (i0 + 0 < NN) ? g_deg[i0 + 0] : 0;
        int d1 = (i0 + 1 < NN) ? g_deg[i0 + 1] : 0;
        int d2 = (i0 + 2 < NN) ? g_deg[i0 + 2] : 0;
        int d3 = (i0 + 3 < NN) ? g_deg[i0 + 3] : 0;
        int v = d0 + d1 + d2 + d3;
        int x = v;
#pragma unroll
        for (int off = 1; off < 32; off <<= 1) {
            int t = __shfl_up_sync(0xffffffffu, x, off);
            if (lane >= off) x += t;
        }
        if (lane == 31) wsum[wid] = x;
        __syncthreads();
        if (wid == 0) {
            int w = wsum[lane];
#pragma unroll
            for (int off = 1; off < 32; off <<= 1) {
                int t = __shfl_up_sync(0xffffffffu, w, off);
                if (lane >= off) w += t;
            }
            wsum[lane] = w;
        }
        __syncthreads();
        int inc = x + (wid > 0 ? wsum[wid - 1] : 0);
        int carry = carryS;
        __syncthreads();
        int excl = carry + inc - v;
        int p0 = excl + d0, p1 = p0 + d1, p2 = p1 + d2, p3 = p2 + d3;
        if (i0 + 0 < NN) { g_rowptr[i0 + 1] = p0; g_ofs[i0 + 0] = excl; }
        if (i0 + 1 < NN) { g_rowptr[i0 + 2] = p1; g_ofs[i0 + 1] = p0; }
        if (i0 + 2 < NN) { g_rowptr[i0 + 3] = p2; g_ofs[i0 + 2] = p1; }
        if (i0 + 3 < NN) { g_rowptr[i0 + 4] = p3; g_ofs[i0 + 3] = p2; }
        if (tid == 1023) carryS = carry + inc;
        __syncthreads();
    }
}

__global__ void k_scatter(const int* __restrict__ ei) {
    int e = blockIdx.x * blockDim.x + threadIdx.x;
    if (e >= ETOT) return;
    int src, dst;
    if (e < EE) { src = ei[e]; dst = ei[EE + e]; } else { src = dst = e - EE; }
    int pos = atomicAdd(&g_ofs[dst], 1);
    g_srcp[pos] = src;
}

// ======== fused GEMM (128->128, f32x2 packed) + attention coefficients ========
// block = 128 thr (4 warps), 16 nodes/block, 4 nodes/warp, 4 cols (2xf32x2)/lane
// templated on input type (fp32 harness x, or fp16 g_feat); core is fp32 FFMA2.
template <typename XT>
__global__ __launch_bounds__(128) void k_gemm_attn(const XT* __restrict__ X,
                                                   const float* __restrict__ W,
                                                   const float* __restrict__ as_,
                                                   const float* __restrict__ ad_) {
    __shared__ __align__(16) float xs[16 * FF];
    int warp = threadIdx.x >> 5, lane = threadIdx.x & 31;
    int nb = blockIdx.x * 16;
    float4* xs4 = (float4*)xs;
    if (sizeof(XT) == 4) {   // fp32 input
        const float4* X4 = (const float4*)((const float*)X + (size_t)nb * FF);
        for (int i = threadIdx.x; i < 16 * 32; i += 128) xs4[i] = X4[i];
    } else {                 // fp16 input -> convert while staging
        const uint2* X2 = (const uint2*)((const __half*)X + (size_t)nb * FF);
        for (int i = threadIdx.x; i < 16 * 32; i += 128) {
            uint2 hv = X2[i];
            float2 f0 = __half22float2(*reinterpret_cast<__half2*>(&hv.x));
            float2 f1 = __half22float2(*reinterpret_cast<__half2*>(&hv.y));
            xs4[i] = make_float4(f0.x, f0.y, f1.x, f1.y);
        }
    }
    __syncthreads();
    ull acc[4][2];
#pragma unroll
    for (int j = 0; j < 4; j++) { acc[j][0] = 0ull; acc[j][1] = 0ull; }
    const ulonglong2* W2 = (const ulonglong2*)W;
    int n0 = warp * 4;
#pragma unroll 4
    for (int k4 = 0; k4 < 32; k4++) {
        float4 xv[4];
#pragma unroll
        for (int j = 0; j < 4; j++) xv[j] = xs4[(n0 + j) * 32 + k4];
#pragma unroll
        for (int c = 0; c < 4; c++) {
            ulonglong2 w = W2[(size_t)(k4 * 4 + c) * 32 + lane];
#pragma unroll
            for (int j = 0; j < 4; j++) {
                float xj = (c == 0) ? xv[j].x : (c == 1) ? xv[j].y : (c == 2) ? xv[j].z : xv[j].w;
                ull xx = pk2(xj);
                acc[j][0] = fma2(w.x, xx, acc[j][0]);
                acc[j][1] = fma2(w.y, xx, acc[j][1]);
            }
        }
    }
    uint2* O2 = (uint2*)g_ht;
    float4 as4 = ((const float4*)as_)[lane];
    float4 ad4 = ((const float4*)ad_)[lane];
#pragma unroll
    for (int j = 0; j < 4; j++) {
        float2 lo = up2(acc[j][0]), hi = up2(acc[j][1]);
        float4 a = make_float4(lo.x, lo.y, hi.x, hi.y);
        uint2 pk;
        *reinterpret_cast<__half2*>(&pk.x) = __floats2half2_rn(a.x, a.y);
        *reinterpret_cast<__half2*>(&pk.y) = __floats2half2_rn(a.z, a.w);
        O2[(size_t)(nb + n0 + j) * 32 + lane] = pk;
        float ps = a.x * as4.x + a.y * as4.y + a.z * as4.z + a.w * as4.w;
        float pd = a.x * ad4.x + a.y * ad4.y + a.z * ad4.z + a.w * ad4.w;
#pragma unroll
        for (int off = 1; off < 8; off <<= 1) {
            ps += __shfl_xor_sync(0xffffffffu, ps, off);
            pd += __shfl_xor_sync(0xffffffffu, pd, off);
        }
        if ((lane & 7) == 0) {
            int h = lane >> 3;
            g_as[(nb + n0 + j) * HH + h] = ps;
            g_ad[(nb + n0 + j) * HH + h] = pd;
        }
    }
}

// ======== CSR aggregation (warp per dst node) + bias + BN + ELU ========
// fp16 gather, fp32 accumulate; optionally fused layer-2 GEMM + attn coefs
template <bool FUSE_L2>
__global__ __launch_bounds__(256) void k_agg4(const float* __restrict__ b,
                                              const float* __restrict__ g,
                                              const float* __restrict__ bb,
                                              const float* __restrict__ rm,
                                              const float* __restrict__ rv,
                                              const float* __restrict__ W2,
                                              const float* __restrict__ as2,
                                              const float* __restrict__ ad2) {
    __shared__ float4 s_ex[8][32];
    __shared__ int s_src[8][32];
    __shared__ float sW2t[NC][FF];
    int wid = threadIdx.x >> 5, lane = threadIdx.x & 31;
    if (FUSE_L2) {
        for (int i = threadIdx.x; i < FF * NC; i += 256) {
            int k = i >> 3, m = i & 7;
            sW2t[m][k] = W2[i];
        }
        __syncthreads();
    }
    int node = blockIdx.x * 8 + wid;
    int start = g_rowptr[node], end = g_rowptr[node + 1];
    float4 ad4 = ((const float4*)g_ad)[node];
    int hh = lane >> 3;
    float4 acc = make_float4(0.f, 0.f, 0.f, 0.f);
    float4 den = make_float4(0.f, 0.f, 0.f, 0.f);
    const uint2* ht2 = (const uint2*)g_ht;
    for (int base = start; base < end; base += 32) {
        int k = base + lane;
        float4 ex = make_float4(0.f, 0.f, 0.f, 0.f);
        int src = 0;
        if (k < end) {
            src = g_srcp[k];
            float4 a = ((const float4*)g_as)[src];
            float4 v;
            v.x = a.x + ad4.x; v.y = a.y + ad4.y; v.z = a.z + ad4.z; v.w = a.w + ad4.w;
            v.x = v.x > 0.f ? v.x : 0.2f * v.x;
            v.y = v.y > 0.f ? v.y : 0.2f * v.y;
            v.z = v.z > 0.f ? v.z : 0.2f * v.z;
            v.w = v.w > 0.f ? v.w : 0.2f * v.w;
            ex.x = __expf(v.x); ex.y = __expf(v.y); ex.z = __expf(v.z); ex.w = __expf(v.w);
            den.x += ex.x; den.y += ex.y; den.z += ex.z; den.w += ex.w;
        }
        s_src[wid][lane] = src;
        s_ex[wid][lane] = ex;
        __syncwarp();
        int cnt = min(32, end - base);
#pragma unroll 8
        for (int j = 0; j < cnt; j++) {
            int sj = s_src[wid][j];
            float al = ((const float*)&s_ex[wid][j])[hh];
            uint2 hv = ht2[(size_t)sj * 32 + lane];
            float2 f0 = __half22float2(*reinterpret_cast<__half2*>(&hv.x));
            float2 f1 = __half22float2(*reinterpret_cast<__half2*>(&hv.y));
            acc.x += al * f0.x; acc.y += al * f0.y;
            acc.z += al * f1.x; acc.w += al * f1.y;
        }
        __syncwarp();
    }
#pragma unroll
    for (int off = 16; off; off >>= 1) {
        den.x += __shfl_xor_sync(0xffffffffu, den.x, off);
        den.y += __shfl_xor_sync(0xffffffffu, den.y, off);
        den.z += __shfl_xor_sync(0xffffffffu, den.z, off);
        den.w += __shfl_xor_sync(0xffffffffu, den.w, off);
    }
    float d = hh == 0 ? den.x : hh == 1 ? den.y : hh == 2 ? den.z : den.w;
    float inv = 1.f / (d + 1e-16f);
    acc.x *= inv; acc.y *= inv; acc.z *= inv; acc.w *= inv;
    // bias + BN(eval) + ELU epilogue
    float4 B = ((const float4*)b)[lane],  G = ((const float4*)g)[lane];
    float4 BB = ((const float4*)bb)[lane], RM = ((const float4*)rm)[lane];
    float4 RV = ((const float4*)rv)[lane];
    float4 v;
    v.x = (acc.x + B.x - RM.x) * rsqrtf(RV.x + 1e-5f) * G.x + BB.x;
    v.y = (acc.y + B.y - RM.y) * rsqrtf(RV.y + 1e-5f) * G.y + BB.y;
    v.z = (acc.z + B.z - RM.z) * rsqrtf(RV.z + 1e-5f) * G.z + BB.z;
    v.w = (acc.w + B.w - RM.w) * rsqrtf(RV.w + 1e-5f) * G.w + BB.w;
    v.x = v.x > 0.f ? v.x : __expf(v.x) - 1.f;
    v.y = v.y > 0.f ? v.y : __expf(v.y) - 1.f;
    v.z = v.z > 0.f ? v.z : __expf(v.z) - 1.f;
    v.w = v.w > 0.f ? v.w : __expf(v.w) - 1.f;
    if (!FUSE_L2) {
        uint2 pk;
        *reinterpret_cast<__half2*>(&pk.x) = __floats2half2_rn(v.x, v.y);
        *reinterpret_cast<__half2*>(&pk.y) = __floats2half2_rn(v.z, v.w);
        ((uint2*)g_feat)[(size_t)node * 32 + lane] = pk;
    } else {
        // layer-2 GEMM: h2[m] = sum_c v[c] * W2[c][m], warp-reduce over lanes
        float h[NC];
#pragma unroll
        for (int m = 0; m < NC; m++) {
            float4 w = ((const float4*)(sW2t[m]))[lane];
            float p = v.x * w.x + v.y * w.y + v.z * w.z + v.w * w.w;
#pragma unroll
            for (int off = 16; off; off >>= 1)
                p += __shfl_xor_sync(0xffffffffu, p, off);
            h[m] = p;
        }
        if (lane == 0) {
            uint4 pk;
            *reinterpret_cast<__half2*>(&pk.x) = __floats2half2_rn(h[0], h[1]);
            *reinterpret_cast<__half2*>(&pk.y) = __floats2half2_rn(h[2], h[3]);
            *reinterpret_cast<__half2*>(&pk.z) = __floats2half2_rn(h[4], h[5]);
            *reinterpret_cast<__half2*>(&pk.w) = __floats2half2_rn(h[6], h[7]);
            ((uint4*)g_h2)[node] = pk;
            float ps = 0.f, pd = 0.f;
#pragma unroll
            for (int m = 0; m < NC; m++) {
                ps += h[m] * as2[m];
                pd += h[m] * ad2[m];
            }
            g_as2[node] = ps;
            g_ad2[node] = pd;
        }
    }
}

// ======== layer 2 CSR aggregation (single pass) + bias + log_softmax ========
__global__ __launch_bounds__(256) void k_agg1_final(const float* __restrict__ b2,
                                                    float* __restrict__ out) {
    int wid = threadIdx.x >> 5, lane = threadIdx.x & 31;
    int node = blockIdx.x * 8 + wid;
    int start = g_rowptr[node], end = g_rowptr[node + 1];
    float adv = g_ad2[node];
    float den = 0.f;
    float4 a0 = make_float4(0.f, 0.f, 0.f, 0.f), a1 = a0;
    const uint4* h2 = (const uint4*)g_h2;
    for (int k = start + lane; k < end; k += 32) {
        int src = g_srcp[k];
        float v = g_as2[src] + adv;
        v = v > 0.f ? v : 0.2f * v;
        float ex = __expf(v);
        den += ex;
        uint4 hv = h2[src];
        float2 f0 = __half22float2(*reinterpret_cast<__half2*>(&hv.x));
        float2 f1 = __half22float2(*reinterpret_cast<__half2*>(&hv.y));
        float2 f2 = __half22float2(*reinterpret_cast<__half2*>(&hv.z));
        float2 f3 = __half22float2(*reinterpret_cast<__half2*>(&hv.w));
        a0.x += ex * f0.x; a0.y += ex * f0.y; a0.z += ex * f1.x; a0.w += ex * f1.y;
        a1.x += ex * f2.x; a1.y += ex * f2.y; a1.z += ex * f3.x; a1.w += ex * f3.y;
    }
#pragma unroll
    for (int off = 16; off; off >>= 1) {
        den  += __shfl_xor_sync(0xffffffffu, den, off);
        a0.x += __shfl_xor_sync(0xffffffffu, a0.x, off);
        a0.y += __shfl_xor_sync(0xffffffffu, a0.y, off);
        a0.z += __shfl_xor_sync(0xffffffffu, a0.z, off);
        a0.w += __shfl_xor_sync(0xffffffffu, a0.w, off);
        a1.x += __shfl_xor_sync(0xffffffffu, a1.x, off);
        a1.y += __shfl_xor_sync(0xffffffffu, a1.y, off);
        a1.z += __shfl_xor_sync(0xffffffffu, a1.z, off);
        a1.w += __shfl_xor_sync(0xffffffffu, a1.w, off);
    }
    if (lane == 0) {
        float inv = 1.f / (den + 1e-16f);
        float v[NC] = { a0.x * inv + b2[0], a0.y * inv + b2[1],
                        a0.z * inv + b2[2], a0.w * inv + b2[3],
                        a1.x * inv + b2[4], a1.y * inv + b2[5],
                        a1.z * inv + b2[6], a1.w * inv + b2[7] };
        float mx = -INFINITY;
#pragma unroll
        for (int j = 0; j < NC; j++) mx = fmaxf(mx, v[j]);
        float s = 0.f;
#pragma unroll
        for (int j = 0; j < NC; j++) s += __expf(v[j] - mx);
        float ls = __logf(s) + mx;
#pragma unroll
        for (int j = 0; j < NC; j++) out[node * NC + j] = v[j] - ls;
    }
}

extern "C" void kernel_launch(void* const* d_in, const int* in_sizes, int n_in,
                              void* d_out, int out_size) {
    const float* x   = (const float*)d_in[0];
    const int*   ei  = (const int*)d_in[1];
    const float* W0  = (const float*)d_in[2];
    const float* as0 = (const float*)d_in[3];
    const float* ad0 = (const float*)d_in[4];
    const float* b0  = (const float*)d_in[5];
    const float* g0  = (const float*)d_in[6];
    const float* bb0 = (const float*)d_in[7];
    const float* rm0 = (const float*)d_in[8];
    const float* rv0 = (const float*)d_in[9];
    const float* W1  = (const float*)d_in[10];
    const float* as1 = (const float*)d_in[11];
    const float* ad1 = (const float*)d_in[12];
    const float* b1  = (const float*)d_in[13];
    const float* g1  = (const float*)d_in[14];
    const float* bb1 = (const float*)d_in[15];
    const float* rm1 = (const float*)d_in[16];
    const float* rv1 = (const float*)d_in[17];
    const float* W2  = (const float*)d_in[18];
    const float* as2 = (const float*)d_in[19];
    const float* ad2 = (const float*)d_in[20];
    const float* b2  = (const float*)d_in[21];
    float* out = (float*)d_out;

    __half* feat_ptr = nullptr;
    cudaGetSymbolAddress((void**)&feat_ptr, g_feat);
    int* deg_ptr = nullptr;
    cudaGetSymbolAddress((void**)&deg_ptr, g_deg);

    // one-time side stream + events for fork-join inside graph capture
    static cudaStream_t s2 = nullptr;
    static cudaEvent_t evFork = nullptr, evJoin = nullptr;
    if (!s2) {
        cudaStreamCreateWithFlags(&s2, cudaStreamNonBlocking);
        cudaEventCreateWithFlags(&evFork, cudaEventDisableTiming);
        cudaEventCreateWithFlags(&evJoin, cudaEventDisableTiming);
    }

    const int TB = 256;

    // ---- fork: CSR build on s2, concurrent with layer-0 GEMM on stream 0 ----
    cudaEventRecord(evFork, 0);
    cudaStreamWaitEvent(s2, evFork, 0);

    cudaMemsetAsync(deg_ptr, 0, NN * sizeof(int), s2);
    k_deg<<<(ETOT + TB - 1) / TB, TB, 0, s2>>>(ei);
    k_scan<<<1, 1024, 0, s2>>>();
    k_scatter<<<(ETOT + TB - 1) / TB, TB, 0, s2>>>(ei);
    cudaEventRecord(evJoin, s2);

    // ======== layer 0 GEMM (independent of CSR) ========
    k_gemm_attn<float><<<NN / 16, 128>>>(x, W0, as0, ad0);

    // ---- join: aggregation needs both CSR and GEMM results ----
    cudaStreamWaitEvent(0, evJoin, 0);

    k_agg4<false><<<NN / 8, TB>>>(b0, g0, bb0, rm0, rv0, nullptr, nullptr, nullptr);

    // ======== layer 1 (+ fused layer-2 GEMM/attn) ========
    k_gemm_attn<__half><<<NN / 16, 128>>>(feat_ptr, W1, as1, ad1);
    k_agg4<true><<<NN / 8, TB>>>(b1, g1, bb1, rm1, rv1, W2, as2, ad2);

    // ======== layer 2 aggregation + log_softmax ========
    k_agg1_final<<<NN / 8, TB>>>(b2, out);
}

// round 16
// speedup vs baseline: 1.3462x; 1.1218x over previous
#include <cuda_runtime.h>
#include <cuda_fp16.h>
#include <stdint.h>
#include <math.h>

#define NN 50000
#define EE 800000
#define ETOT (EE + NN)      // edges + self loops
#define FF 128              // HEADS*HID = F_IN
#define HH 4
#define NC 8
#define XS 136              // smem row stride in halves (272B: conflict-free ldmatrix)

typedef unsigned long long ull;

// ---- scratch (device globals; no allocation allowed) ----
__device__ __align__(16) __half g_ht[(size_t)NN * FF];   // transformed features (fp16)
__device__ __align__(16) __half g_feat[(size_t)NN * FF]; // layer-0 output (fp16)
__device__ __align__(16) __half g_h2[NN * NC];           // layer-2 transformed (fp16)
__device__ __align__(16) __half g_Wh0[FF * FF];          // W0 fp16
__device__ __align__(16) __half g_Wh1[FF * FF];          // W1 fp16
__device__ __align__(16) float g_as[NN * HH];
__device__ __align__(16) float g_ad[NN * HH];
__device__ __align__(16) float g_as2[NN];
__device__ __align__(16) float g_ad2[NN];
__device__ int g_srcp[ETOT];        // src per edge, sorted by dst (CSR)
__device__ int g_rowptr[NN + 1];    // CSR row pointers (by dst)
__device__ int g_deg[NN];
__device__ int g_ofs[NN];           // scatter cursors

__device__ __forceinline__ unsigned int smem_u32(const void* p) {
    return (unsigned int)__cvta_generic_to_shared(p);
}

// ================= CSR construction =================
__global__ void k_deg(const int* __restrict__ ei) {
    int e = blockIdx.x * blockDim.x + threadIdx.x;
    if (e >= ETOT) return;
    int dst = (e < EE) ? ei[EE + e] : e - EE;
    atomicAdd(&g_deg[dst], 1);
}

// single-block scan, 4 elements/thread, chunked with carry
__global__ void k_scan() {
    __shared__ int wsum[32];
    __shared__ int carryS;
    int tid = threadIdx.x, lane = tid & 31, wid = tid >> 5;
    if (tid == 0) { carryS = 0; g_rowptr[0] = 0; }
    __syncthreads();
    for (int base = 0; base < NN; base += 4096) {
        int i0 = base + tid * 4;
        int d0 = (i0 + 0 < NN) ? g_deg[i0 + 0] : 0;
        int d1 = (i0 + 1 < NN) ? g_deg[i0 + 1] : 0;
        int d2 = (i0 + 2 < NN) ? g_deg[i0 + 2] : 0;
        int d3 = (i0 + 3 < NN) ? g_deg[i0 + 3] : 0;
        int v = d0 + d1 + d2 + d3;
        int x = v;
#pragma unroll
        for (int off = 1; off < 32; off <<= 1) {
            int t = __shfl_up_sync(0xffffffffu, x, off);
            if (lane >= off) x += t;
        }
        if (lane == 31) wsum[wid] = x;
        __syncthreads();
        if (wid == 0) {
            int w = wsum[lane];
#pragma unroll
            for (int off = 1; off < 32; off <<= 1) {
                int t = __shfl_up_sync(0xffffffffu, w, off);
                if (lane >= off) w += t;
            }
            wsum[lane] = w;
        }
        __syncthreads();
        int inc = x + (wid > 0 ? wsum[wid - 1] : 0);
        int carry = carryS;
        __syncthreads();
        int excl = carry + inc - v;
        int p0 = excl + d0, p1 = p0 + d1, p2 = p1 + d2, p3 = p2 + d3;
        if (i0 + 0 < NN) { g_rowptr[i0 + 1] = p0; g_ofs[i0 + 0] = excl; }
        if (i0 + 1 < NN) { g_rowptr[i0 + 2] = p1; g_ofs[i0 + 1] = p0; }
        if (i0 + 2 < NN) { g_rowptr[i0 + 3] = p2; g_ofs[i0 + 2] = p1; }
        if (i0 + 3 < NN) { g_rowptr[i0 + 4] = p3; g_ofs[i0 + 3] = p2; }
        if (tid == 1023) carryS = carry + inc;
        __syncthreads();
    }
}

__global__ void k_scatter(const int* __restrict__ ei) {
    int e = blockIdx.x * blockDim.x + threadIdx.x;
    if (e >= ETOT) return;
    int src, dst;
    if (e < EE) { src = ei[e]; dst = ei[EE + e]; } else { src = dst = e - EE; }
    int pos = atomicAdd(&g_ofs[dst], 1);
    g_srcp[pos] = src;
}

// ================= weight fp32 -> fp16 conversion (once) =================
__global__ void k_cvtW(const float* __restrict__ W0, const float* __restrict__ W1) {
    int i = blockIdx.x * blockDim.x + threadIdx.x;
    if (i < FF * FF) {
        g_Wh0[i] = __float2half_rn(W0[i]);
        g_Wh1[i] = __float2half_rn(W1[i]);
    }
}

// ======== tensor-core GEMM (128->128, mma.sync f16 -> f32) + attention coefs ========
// block = 128 thr (4 warps); 32 nodes x 128 cols per block; warp = 16 nodes x 64 cols.
template <typename XT>
__global__ __launch_bounds__(128) void k_gemm_attn(const XT* __restrict__ X,
                                                   const __half* __restrict__ Wh,
                                                   const float* __restrict__ as_,
                                                   const float* __restrict__ ad_) {
    __shared__ __align__(16) __half ws[FF * XS];    // W: 128 x 128 (+pad)
    __shared__ __align__(16) __half xsh[32 * XS];   // x: 32 x 128 (+pad), reused for h-out
    int tid = threadIdx.x;
    int warp = tid >> 5, lane = tid & 31;
    int nb = blockIdx.x * 32;

    // stage W (k-major rows of 128 halves)
    const uint4* Wv = (const uint4*)Wh;
    for (int i = tid; i < FF * FF / 8; i += 128) {
        int r = i >> 4, c8 = i & 15;
        ((uint4*)(ws + r * XS))[c8] = Wv[i];
    }
    // stage x as fp16
    if (sizeof(XT) == 4) {
        const float4* X4 = (const float4*)X;
        for (int i = tid; i < 32 * 32; i += 128) {
            int r = i >> 5, c4 = i & 31;
            float4 v = (nb + r < NN) ? X4[(size_t)(nb + r) * 32 + c4]
                                     : make_float4(0.f, 0.f, 0.f, 0.f);
            *(__half2*)(xsh + r * XS + c4 * 4)     = __floats2half2_rn(v.x, v.y);
            *(__half2*)(xsh + r * XS + c4 * 4 + 2) = __floats2half2_rn(v.z, v.w);
        }
    } else {
        const uint4* X8 = (const uint4*)X;
        for (int i = tid; i < 32 * 16; i += 128) {
            int r = i >> 4, c8 = i & 15;
            uint4 v = (nb + r < NN) ? X8[(size_t)(nb + r) * 16 + c8]
                                    : make_uint4(0u, 0u, 0u, 0u);
            ((uint4*)(xsh + r * XS))[c8] = v;
        }
    }
    __syncthreads();

    int wm = (warp >> 1) * 16;   // node offset in block
    int wn = (warp & 1) * 64;    // col offset
    float d[8][4];
#pragma unroll
    for (int t = 0; t < 8; t++) { d[t][0] = 0.f; d[t][1] = 0.f; d[t][2] = 0.f; d[t][3] = 0.f; }

    unsigned int a_base = smem_u32(xsh + (wm + (lane & 15)) * XS + ((lane >> 4) << 3));
    unsigned int b_base = smem_u32(ws + (lane & 15) * XS + wn + ((lane >> 4) << 3));

#pragma unroll
    for (int ks = 0; ks < 8; ks++) {
        unsigned int a0, a1, a2, a3;
        asm volatile("ldmatrix.sync.aligned.m8n8.x4.shared.b16 {%0,%1,%2,%3}, [%4];"
                     : "=r"(a0), "=r"(a1), "=r"(a2), "=r"(a3)
                     : "r"(a_base + ks * 32));
#pragma unroll
        for (int p = 0; p < 4; p++) {
            unsigned int b0, b1, b2, b3;
            asm volatile("ldmatrix.sync.aligned.m8n8.x4.trans.shared.b16 {%0,%1,%2,%3}, [%4];"
                         : "=r"(b0), "=r"(b1), "=r"(b2), "=r"(b3)
                         : "r"(b_base + ks * (16 * XS * 2) + p * 32));
            int t = p * 2;
            asm volatile("mma.sync.aligned.m16n8k16.row.col.f32.f16.f16.f32 "
                         "{%0,%1,%2,%3}, {%4,%5,%6,%7}, {%8,%9}, {%0,%1,%2,%3};"
                         : "+f"(d[t][0]), "+f"(d[t][1]), "+f"(d[t][2]), "+f"(d[t][3])
                         : "r"(a0), "r"(a1), "r"(a2), "r"(a3), "r"(b0), "r"(b1));
            asm volatile("mma.sync.aligned.m16n8k16.row.col.f32.f16.f16.f32 "
                         "{%0,%1,%2,%3}, {%4,%5,%6,%7}, {%8,%9}, {%0,%1,%2,%3};"
                         : "+f"(d[t+1][0]), "+f"(d[t+1][1]), "+f"(d[t+1][2]), "+f"(d[t+1][3])
                         : "r"(a0), "r"(a1), "r"(a2), "r"(a3), "r"(b2), "r"(b3));
        }
    }
    __syncthreads();   // xsh (x) fully consumed; reuse as h-out buffer

    // D frags -> smem fp16: lane row = lane/4 (+8), cols 2*(lane%4) (+1)
#pragma unroll
    for (int t = 0; t < 8; t++) {
        int col = wn + t * 8 + 2 * (lane & 3);
        int r0 = wm + (lane >> 2);
        *(__half2*)(xsh + r0 * XS + col)       = __floats2half2_rn(d[t][0], d[t][1]);
        *(__half2*)(xsh + (r0 + 8) * XS + col) = __floats2half2_rn(d[t][2], d[t][3]);
    }
    __syncthreads();

    // coalesced write to g_ht
    for (int i = tid; i < 32 * 16; i += 128) {
        int r = i >> 4, c8 = i & 15;
        if (nb + r < NN)
            ((uint4*)((__half*)g_ht + (size_t)(nb + r) * FF))[c8] =
                ((uint4*)(xsh + r * XS))[c8];
    }
    // attention coefficients: thread = (node, head); head = 32-col quarter
    {
        int node = tid >> 2, head = tid & 3;
        if (nb + node < NN) {
            const __half2* hrow = (const __half2*)(xsh + node * XS + head * 32);
            const float* av = as_ + head * 32;
            const float* dv = ad_ + head * 32;
            float ps = 0.f, pd = 0.f;
#pragma unroll
            for (int c = 0; c < 16; c++) {
                float2 h = __half22float2(hrow[c]);
                ps += h.x * av[2 * c] + h.y * av[2 * c + 1];
                pd += h.x * dv[2 * c] + h.y * dv[2 * c + 1];
            }
            g_as[(nb + node) * HH + head] = ps;
            g_ad[(nb + node) * HH + head] = pd;
        }
    }
}

// ======== CSR aggregation (warp per dst node) + bias + BN + ELU ========
// fp16 gather, fp32 accumulate; optionally fused layer-2 GEMM + attn coefs
template <bool FUSE_L2>
__global__ __launch_bounds__(256) void k_agg4(const float* __restrict__ b,
                                              const float* __restrict__ g,
                                              const float* __restrict__ bb,
                                              const float* __restrict__ rm,
                                              const float* __restrict__ rv,
                                              const float* __restrict__ W2,
                                              const float* __restrict__ as2,
                                              const float* __restrict__ ad2) {
    __shared__ float4 s_ex[8][32];
    __shared__ int s_src[8][32];
    __shared__ float sW2t[NC][FF];
    int wid = threadIdx.x >> 5, lane = threadIdx.x & 31;
    if (FUSE_L2) {
        for (int i = threadIdx.x; i < FF * NC; i += 256) {
            int k = i >> 3, m = i & 7;
            sW2t[m][k] = W2[i];
        }
        __syncthreads();
    }
    int node = blockIdx.x * 8 + wid;
    int start = g_rowptr[node], end = g_rowptr[node + 1];
    float4 ad4 = ((const float4*)g_ad)[node];
    int hh = lane >> 3;
    float4 acc = make_float4(0.f, 0.f, 0.f, 0.f);
    float4 den = make_float4(0.f, 0.f, 0.f, 0.f);
    const uint2* ht2 = (const uint2*)g_ht;
    for (int base = start; base < end; base += 32) {
        int k = base + lane;
        float4 ex = make_float4(0.f, 0.f, 0.f, 0.f);
        int src = 0;
        if (k < end) {
            src = g_srcp[k];
            float4 a = ((const float4*)g_as)[src];
            float4 v;
            v.x = a.x + ad4.x; v.y = a.y + ad4.y; v.z = a.z + ad4.z; v.w = a.w + ad4.w;
            v.x = v.x > 0.f ? v.x : 0.2f * v.x;
            v.y = v.y > 0.f ? v.y : 0.2f * v.y;
            v.z = v.z > 0.f ? v.z : 0.2f * v.z;
            v.w = v.w > 0.f ? v.w : 0.2f * v.w;
            ex.x = __expf(v.x); ex.y = __expf(v.y); ex.z = __expf(v.z); ex.w = __expf(v.w);
            den.x += ex.x; den.y += ex.y; den.z += ex.z; den.w += ex.w;
        }
        s_src[wid][lane] = src;
        s_ex[wid][lane] = ex;
        __syncwarp();
        int cnt = min(32, end - base);
#pragma unroll 8
        for (int j = 0; j < cnt; j++) {
            int sj = s_src[wid][j];
            float al = ((const float*)&s_ex[wid][j])[hh];
            uint2 hv = ht2[(size_t)sj * 32 + lane];
            float2 f0 = __half22float2(*reinterpret_cast<__half2*>(&hv.x));
            float2 f1 = __half22float2(*reinterpret_cast<__half2*>(&hv.y));
            acc.x += al * f0.x; acc.y += al * f0.y;
            acc.z += al * f1.x; acc.w += al * f1.y;
        }
        __syncwarp();
    }
#pragma unroll
    for (int off = 16; off; off >>= 1) {
        den.x += __shfl_xor_sync(0xffffffffu, den.x, off);
        den.y += __shfl_xor_sync(0xffffffffu, den.y, off);
        den.z += __shfl_xor_sync(0xffffffffu, den.z, off);
        den.w += __shfl_xor_sync(0xffffffffu, den.w, off);
    }
    float d = hh == 0 ? den.x : hh == 1 ? den.y : hh == 2 ? den.z : den.w;
    float inv = 1.f / (d + 1e-16f);
    acc.x *= inv; acc.y *= inv; acc.z *= inv; acc.w *= inv;
    // bias + BN(eval) + ELU epilogue
    float4 B = ((const float4*)b)[lane],  G = ((const float4*)g)[lane];
    float4 BB = ((const float4*)bb)[lane], RM = ((const float4*)rm)[lane];
    float4 RV = ((const float4*)rv)[lane];
    float4 v;
    v.x = (acc.x + B.x - RM.x) * rsqrtf(RV.x + 1e-5f) * G.x + BB.x;
    v.y = (acc.y + B.y - RM.y) * rsqrtf(RV.y + 1e-5f) * G.y + BB.y;
    v.z = (acc.z + B.z - RM.z) * rsqrtf(RV.z + 1e-5f) * G.z + BB.z;
    v.w = (acc.w + B.w - RM.w) * rsqrtf(RV.w + 1e-5f) * G.w + BB.w;
    v.x = v.x > 0.f ? v.x : __expf(v.x) - 1.f;
    v.y = v.y > 0.f ? v.y : __expf(v.y) - 1.f;
    v.z = v.z > 0.f ? v.z : __expf(v.z) - 1.f;
    v.w = v.w > 0.f ? v.w : __expf(v.w) - 1.f;
    if (!FUSE_L2) {
        uint2 pk;
        *reinterpret_cast<__half2*>(&pk.x) = __floats2half2_rn(v.x, v.y);
        *reinterpret_cast<__half2*>(&pk.y) = __floats2half2_rn(v.z, v.w);
        ((uint2*)g_feat)[(size_t)node * 32 + lane] = pk;
    } else {
        float h[NC];
#pragma unroll
        for (int m = 0; m < NC; m++) {
            float4 w = ((const float4*)(sW2t[m]))[lane];
            float p = v.x * w.x + v.y * w.y + v.z * w.z + v.w * w.w;
#pragma unroll
            for (int off = 16; off; off >>= 1)
                p += __shfl_xor_sync(0xffffffffu, p, off);
            h[m] = p;
        }
        if (lane == 0) {
            uint4 pk;
            *reinterpret_cast<__half2*>(&pk.x) = __floats2half2_rn(h[0], h[1]);
            *reinterpret_cast<__half2*>(&pk.y) = __floats2half2_rn(h[2], h[3]);
            *reinterpret_cast<__half2*>(&pk.z) = __floats2half2_rn(h[4], h[5]);
            *reinterpret_cast<__half2*>(&pk.w) = __floats2half2_rn(h[6], h[7]);
            ((uint4*)g_h2)[node] = pk;
            float ps = 0.f, pd = 0.f;
#pragma unroll
            for (int m = 0; m < NC; m++) {
                ps += h[m] * as2[m];
                pd += h[m] * ad2[m];
            }
            g_as2[node] = ps;
            g_ad2[node] = pd;
        }
    }
}

// ======== layer 2 CSR aggregation (single pass) + bias + log_softmax ========
__global__ __launch_bounds__(256) void k_agg1_final(const float* __restrict__ b2,
                                                    float* __restrict__ out) {
    int wid = threadIdx.x >> 5, lane = threadIdx.x & 31;
    int node = blockIdx.x * 8 + wid;
    int start = g_rowptr[node], end = g_rowptr[node + 1];
    float adv = g_ad2[node];
    float den = 0.f;
    float4 a0 = make_float4(0.f, 0.f, 0.f, 0.f), a1 = a0;
    const uint4* h2 = (const uint4*)g_h2;
    for (int k = start + lane; k < end; k += 32) {
        int src = g_srcp[k];
        float v = g_as2[src] + adv;
        v = v > 0.f ? v : 0.2f * v;
        float ex = __expf(v);
        den += ex;
        uint4 hv = h2[src];
        float2 f0 = __half22float2(*reinterpret_cast<__half2*>(&hv.x));
        float2 f1 = __half22float2(*reinterpret_cast<__half2*>(&hv.y));
        float2 f2 = __half22float2(*reinterpret_cast<__half2*>(&hv.z));
        float2 f3 = __half22float2(*reinterpret_cast<__half2*>(&hv.w));
        a0.x += ex * f0.x; a0.y += ex * f0.y; a0.z += ex * f1.x; a0.w += ex * f1.y;
        a1.x += ex * f2.x; a1.y += ex * f2.y; a1.z += ex * f3.x; a1.w += ex * f3.y;
    }
#pragma unroll
    for (int off = 16; off; off >>= 1) {
        den  += __shfl_xor_sync(0xffffffffu, den, off);
        a0.x += __shfl_xor_sync(0xffffffffu, a0.x, off);
        a0.y += __shfl_xor_sync(0xffffffffu, a0.y, off);
        a0.z += __shfl_xor_sync(0xffffffffu, a0.z, off);
        a0.w += __shfl_xor_sync(0xffffffffu, a0.w, off);
        a1.x += __shfl_xor_sync(0xffffffffu, a1.x, off);
        a1.y += __shfl_xor_sync(0xffffffffu, a1.y, off);
        a1.z += __shfl_xor_sync(0xffffffffu, a1.z, off);
        a1.w += __shfl_xor_sync(0xffffffffu, a1.w, off);
    }
    if (lane == 0) {
        float inv = 1.f / (den + 1e-16f);
        float v[NC] = { a0.x * inv + b2[0], a0.y * inv + b2[1],
                        a0.z * inv + b2[2], a0.w * inv + b2[3],
                        a1.x * inv + b2[4], a1.y * inv + b2[5],
                        a1.z * inv + b2[6], a1.w * inv + b2[7] };
        float mx = -INFINITY;
#pragma unroll
        for (int j = 0; j < NC; j++) mx = fmaxf(mx, v[j]);
        float s = 0.f;
#pragma unroll
        for (int j = 0; j < NC; j++) s += __expf(v[j] - mx);
        float ls = __logf(s) + mx;
#pragma unroll
        for (int j = 0; j < NC; j++) out[node * NC + j] = v[j] - ls;
    }
}

extern "C" void kernel_launch(void* const* d_in, const int* in_sizes, int n_in,
                              void* d_out, int out_size) {
    const float* x   = (const float*)d_in[0];
    const int*   ei  = (const int*)d_in[1];
    const float* W0  = (const float*)d_in[2];
    const float* as0 = (const float*)d_in[3];
    const float* ad0 = (const float*)d_in[4];
    const float* b0  = (const float*)d_in[5];
    const float* g0  = (const float*)d_in[6];
    const float* bb0 = (const float*)d_in[7];
    const float* rm0 = (const float*)d_in[8];
    const float* rv0 = (const float*)d_in[9];
    const float* W1  = (const float*)d_in[10];
    const float* as1 = (const float*)d_in[11];
    const float* ad1 = (const float*)d_in[12];
    const float* b1  = (const float*)d_in[13];
    const float* g1  = (const float*)d_in[14];
    const float* bb1 = (const float*)d_in[15];
    const float* rm1 = (const float*)d_in[16];
    const float* rv1 = (const float*)d_in[17];
    const float* W2  = (const float*)d_in[18];
    const float* as2 = (const float*)d_in[19];
    const float* ad2 = (const float*)d_in[20];
    const float* b2  = (const float*)d_in[21];
    float* out = (float*)d_out;

    __half *feat_ptr, *wh0, *wh1;
    int* deg_ptr;
    cudaGetSymbolAddress((void**)&feat_ptr, g_feat);
    cudaGetSymbolAddress((void**)&wh0, g_Wh0);
    cudaGetSymbolAddress((void**)&wh1, g_Wh1);
    cudaGetSymbolAddress((void**)&deg_ptr, g_deg);

    // one-time side stream + events for fork-join inside graph capture
    static cudaStream_t s2 = nullptr;
    static cudaEvent_t evFork = nullptr, evJoin = nullptr;
    if (!s2) {
        cudaStreamCreateWithFlags(&s2, cudaStreamNonBlocking);
        cudaEventCreateWithFlags(&evFork, cudaEventDisableTiming);
        cudaEventCreateWithFlags(&evJoin, cudaEventDisableTiming);
    }

    const int TB = 256;

    // ---- fork: CSR build on s2, concurrent with W-convert + layer-0 GEMM ----
    cudaEventRecord(evFork, 0);
    cudaStreamWaitEvent(s2, evFork, 0);

    cudaMemsetAsync(deg_ptr, 0, NN * sizeof(int), s2);
    k_deg<<<(ETOT + TB - 1) / TB, TB, 0, s2>>>(ei);
    k_scan<<<1, 1024, 0, s2>>>();
    k_scatter<<<(ETOT + TB - 1) / TB, TB, 0, s2>>>(ei);
    cudaEventRecord(evJoin, s2);

    // ======== W conversion + layer 0 GEMM (independent of CSR) ========
    k_cvtW<<<(FF * FF + TB - 1) / TB, TB>>>(W0, W1);
    k_gemm_attn<float><<<(NN + 31) / 32, 128>>>(x, wh0, as0, ad0);

    // ---- join: aggregation needs both CSR and GEMM results ----
    cudaStreamWaitEvent(0, evJoin, 0);

    k_agg4<false><<<NN / 8, TB>>>(b0, g0, bb0, rm0, rv0, nullptr, nullptr, nullptr);

    // ======== layer 1 (+ fused layer-2 GEMM/attn) ========
    k_gemm_attn<__half><<<(NN + 31) / 32, 128>>>(feat_ptr, wh1, as1, ad1);
    k_agg4<true><<<NN / 8, TB>>>(b1, g1, bb1, rm1, rv1, W2, as2, ad2);

    // ======== layer 2 aggregation + log_softmax ========
    k_agg1_final<<<NN / 8, TB>>>(b2, out);
}